// round 1
// baseline (speedup 1.0000x reference)
#include <cuda_runtime.h>

#define NN 25000
#define EE 400000

// Scratch: Z[j][k][h], fp32, 25000 * 1024 floats = 102.4 MB
__device__ float g_Z[NN * 1024];

// ---------------------------------------------------------------------------
// K1: Z = x @ G where G[d][c] (c = k*32+h) = edge_W[(d*32+h)*32 + k]
//     plus out init: out = x @ node_W^T
// Block: 256 threads, 64 nodes. G staged in smem with 128B XOR swizzle so the
// k<->h transpose has no 32-way STS conflicts and compute reads are LDS.128.
// ---------------------------------------------------------------------------
__global__ void __launch_bounds__(256, 1)
k1_build_Z(const float* __restrict__ x, const float* __restrict__ edge_W,
           const float* __restrict__ node_W, float* __restrict__ out) {
    extern __shared__ float sm[];
    float* Gs  = sm;               // 32 rows x 1024 cols (swizzled), 128 KB
    float* xs  = Gs + 32 * 1024;   // x transposed [32][72]
    float* nws = xs + 32 * 72;     // node_W [32][33]

    const int t  = threadIdx.x;
    const int tx = t & 31;
    const int ty = t >> 5;         // 0..7 (warp id)
    const int node0 = blockIdx.x * 64;

    // Stage edge_W -> Gs, transposing (h,k)->(k,h) inside each d-block.
    // Source read is fully coalesced; dest uses 128B XOR swizzle.
    for (int i = t; i < 32 * 1024; i += 256) {
        const int d   = i >> 10;
        const int rem = i & 1023;
        const int h   = rem >> 5;
        const int k   = rem & 31;
        const int cb  = ((k << 5) | h) << 2;        // byte offset in 4KB row
        const int sw  = cb ^ ((cb >> 3) & 0x70);    // SW128 swizzle
        Gs[(d << 10) + (sw >> 2)] = edge_W[i];
    }
    // Stage x transposed: xs[d][jl]
    for (int i = t; i < 64 * 8; i += 256) {
        const int jl = i >> 3;
        const int d4 = (i & 7) << 2;
        const int j  = node0 + jl;
        float4 v = make_float4(0.f, 0.f, 0.f, 0.f);
        if (j < NN) v = *reinterpret_cast<const float4*>(x + j * 32 + d4);
        xs[(d4 + 0) * 72 + jl] = v.x;
        xs[(d4 + 1) * 72 + jl] = v.y;
        xs[(d4 + 2) * 72 + jl] = v.z;
        xs[(d4 + 3) * 72 + jl] = v.w;
    }
    // Stage node_W with +1 pad
    for (int i = t; i < 1024; i += 256) {
        nws[(i >> 5) * 33 + (i & 31)] = node_W[i];
    }
    __syncthreads();

    // out init: warp ty handles nodes node0+ty*8 .. +7, lane tx = h
    {
        float accn[8];
#pragma unroll
        for (int n = 0; n < 8; n++) accn[n] = 0.f;
#pragma unroll 4
        for (int d = 0; d < 32; d++) {
            const float w = nws[tx * 33 + d];
#pragma unroll
            for (int n = 0; n < 8; n++)
                accn[n] += xs[d * 72 + ty * 8 + n] * w;
        }
#pragma unroll
        for (int n = 0; n < 8; n++) {
            const int j = node0 + ty * 8 + n;
            if (j < NN) out[j * 32 + tx] = accn[n];
        }
    }

    // Main Z GEMM: 8 col-tiles of 128; each thread: 8 nodes x 4 cols
    for (int tile = 0; tile < 8; tile++) {
        const int c   = tile * 128 + tx * 4;
        const int cb  = c << 2;
        const int swi = (cb ^ ((cb >> 3) & 0x70)) >> 2;  // swizzled word idx
        float acc[8][4];
#pragma unroll
        for (int n = 0; n < 8; n++)
#pragma unroll
            for (int i = 0; i < 4; i++) acc[n][i] = 0.f;

#pragma unroll 4
        for (int d = 0; d < 32; d++) {
            const float4 b  = *reinterpret_cast<const float4*>(&Gs[(d << 10) + swi]);
            const float4 a0 = *reinterpret_cast<const float4*>(&xs[d * 72 + ty * 8]);
            const float4 a1 = *reinterpret_cast<const float4*>(&xs[d * 72 + ty * 8 + 4]);
            const float a[8] = {a0.x, a0.y, a0.z, a0.w, a1.x, a1.y, a1.z, a1.w};
#pragma unroll
            for (int n = 0; n < 8; n++) {
                acc[n][0] += a[n] * b.x;
                acc[n][1] += a[n] * b.y;
                acc[n][2] += a[n] * b.z;
                acc[n][3] += a[n] * b.w;
            }
        }
#pragma unroll
        for (int n = 0; n < 8; n++) {
            const int j = node0 + ty * 8 + n;
            if (j < NN)
                *reinterpret_cast<float4*>(&g_Z[j * 1024 + c]) =
                    make_float4(acc[n][0], acc[n][1], acc[n][2], acc[n][3]);
        }
    }
}

// ---------------------------------------------------------------------------
// K2: per-edge msgs[e,h] = sum_k ea[e,k] * Z[src_e,k,h], scatter-add to dst.
// Warp per edge; Z[src] row (4KB) gathered with 8x coalesced LDG.128.
// Lane l holds h-quad (l&7)*4, k residue l>>3 (mod 4); butterfly over
// lanes^8,^16 completes the k-sum; lanes 0..7 emit one red.global.add.v4.f32.
// ---------------------------------------------------------------------------
__global__ void __launch_bounds__(256)
k2_edges(const float* __restrict__ ea, const int* __restrict__ ei,
         float* __restrict__ out) {
    const int e    = blockIdx.x * 8 + (threadIdx.x >> 5);
    const int lane = threadIdx.x & 31;
    if (e >= EE) return;

    const int src = ei[e];
    const int dst = ei[EE + e];
    const float eav = ea[e * 32 + lane];

    const float4* Zp = reinterpret_cast<const float4*>(g_Z + src * 1024);
    float4 acc = make_float4(0.f, 0.f, 0.f, 0.f);
#pragma unroll
    for (int i = 0; i < 8; i++) {
        const float4 z = Zp[i * 32 + lane];
        const float ek = __shfl_sync(0xffffffffu, eav, i * 4 + (lane >> 3));
        acc.x += ek * z.x;
        acc.y += ek * z.y;
        acc.z += ek * z.z;
        acc.w += ek * z.w;
    }
    // reduce partial k-sums across the 4 lanes sharing an h-quad
    acc.x += __shfl_xor_sync(0xffffffffu, acc.x, 8);
    acc.y += __shfl_xor_sync(0xffffffffu, acc.y, 8);
    acc.z += __shfl_xor_sync(0xffffffffu, acc.z, 8);
    acc.w += __shfl_xor_sync(0xffffffffu, acc.w, 8);
    acc.x += __shfl_xor_sync(0xffffffffu, acc.x, 16);
    acc.y += __shfl_xor_sync(0xffffffffu, acc.y, 16);
    acc.z += __shfl_xor_sync(0xffffffffu, acc.z, 16);
    acc.w += __shfl_xor_sync(0xffffffffu, acc.w, 16);

    if (lane < 8) {
        float* p = out + dst * 32 + lane * 4;
        asm volatile("red.global.add.v4.f32 [%0], {%1,%2,%3,%4};"
                     :: "l"(p), "f"(acc.x), "f"(acc.y), "f"(acc.z), "f"(acc.w)
                     : "memory");
    }
}

// ---------------------------------------------------------------------------
extern "C" void kernel_launch(void* const* d_in, const int* in_sizes, int n_in,
                              void* d_out, int out_size) {
    const float* x          = (const float*)d_in[0];  // [25000,32]
    const float* edge_attr  = (const float*)d_in[1];  // [400000,32]
    const float* edge_W     = (const float*)d_in[2];  // [1024,32]
    const float* node_W     = (const float*)d_in[3];  // [32,32]
    const int*   edge_index = (const int*)d_in[4];    // [2,400000]
    float* out = (float*)d_out;

    const size_t smem1 = (32 * 1024 + 32 * 72 + 32 * 33) * sizeof(float); // 144.5 KB
    cudaFuncSetAttribute(k1_build_Z, cudaFuncAttributeMaxDynamicSharedMemorySize,
                         (int)smem1);

    // K1 initializes out (= x @ node_W^T) and builds Z; K2 scatter-adds msgs.
    k1_build_Z<<<(NN + 63) / 64, 256, smem1>>>(x, edge_W, node_W, out);
    k2_edges<<<EE / 8, 256>>>(edge_attr, edge_index, out);
}